// round 3
// baseline (speedup 1.0000x reference)
#include <cuda_runtime.h>
#include <cuda_bf16.h>
#include <cstdint>

#define DD 128
#define NMAX 50176
#define EMAX 800256

// ---------------- scratch (__device__ globals; no allocation) ----------------
__device__ float          g_ht[(size_t)NMAX * DD];     // post-linear h (fp32, row-major)
__device__ __nv_bfloat16  g_ahi[(size_t)NMAX * DD];    // A fragments, hi (per-lane mma order)
__device__ __nv_bfloat16  g_alo[(size_t)NMAX * DD];    // A fragments, lo
__device__ __nv_bfloat16  g_bhi[3][DD * DD];           // B fragments, hi (per layer)
__device__ __nv_bfloat16  g_blo[3][DD * DD];           // B fragments, lo
__device__ float          g_sl[NMAX], g_sr[NMAX];
__device__ int            g_deg[NMAX];
__device__ int            g_off[NMAX + 1];
__device__ int            g_pos[NMAX];
__device__ int            g_col[EMAX];

// ---------------- helpers ----------------
static __device__ __forceinline__ unsigned short bfbits(float v) {
    __nv_bfloat16 b = __float2bfloat16(v);
    return *reinterpret_cast<unsigned short*>(&b);
}
static __device__ __forceinline__ float bfval(float v) {
    return __bfloat162float(__float2bfloat16(v));
}
static __device__ __forceinline__ uint32_t pack_hi(float a, float b) {
    return (uint32_t)bfbits(a) | ((uint32_t)bfbits(b) << 16);
}
static __device__ __forceinline__ uint32_t pack_lo(float a, float b) {
    return (uint32_t)bfbits(a - bfval(a)) | ((uint32_t)bfbits(b - bfval(b)) << 16);
}

static __device__ __forceinline__ void mma16816(float* c, const uint32_t* a, const uint32_t* b) {
    asm volatile(
        "mma.sync.aligned.m16n8k16.row.col.f32.bf16.bf16.f32 "
        "{%0,%1,%2,%3}, {%4,%5,%6,%7}, {%8,%9}, {%0,%1,%2,%3};"
        : "+f"(c[0]), "+f"(c[1]), "+f"(c[2]), "+f"(c[3])
        : "r"(a[0]), "r"(a[1]), "r"(a[2]), "r"(a[3]), "r"(b[0]), "r"(b[1]));
}

// ---------------- CSR build ----------------
__global__ void k_zero(int N) {
    int i = blockIdx.x * blockDim.x + threadIdx.x;
    if (i < N) g_deg[i] = 0;
}
__global__ void k_count(const int* __restrict__ src, int E) {
    int e = blockIdx.x * blockDim.x + threadIdx.x;
    if (e < E) atomicAdd(&g_deg[src[e]], 1);
}
__global__ __launch_bounds__(1024) void k_scan(int N, int E) {
    __shared__ int sh[1024];
    int tid = threadIdx.x;
    int per = (N + 1023) >> 10;
    int s = tid * per;
    int e = s + per; if (e > N) e = N;
    int sum = 0;
    for (int i = s; i < e; i++) sum += g_deg[i];
    sh[tid] = sum;
    __syncthreads();
    for (int o = 1; o < 1024; o <<= 1) {
        int t = (tid >= o) ? sh[tid - o] : 0;
        __syncthreads();
        sh[tid] += t;
        __syncthreads();
    }
    int run = sh[tid] - sum;
    for (int i = s; i < e; i++) { g_off[i] = run; g_pos[i] = run; run += g_deg[i]; }
    if (tid == 1023) g_off[N] = E;
}
__global__ void k_scatter(const int* __restrict__ src, const int* __restrict__ dst, int E) {
    int e = blockIdx.x * blockDim.x + threadIdx.x;
    if (e < E) {
        int p = atomicAdd(&g_pos[src[e]], 1);
        g_col[p] = dst[e];
    }
}

// ---------------- fragment preparation ----------------
// A fragment order: uint4 index ((t*8 + s)*32 + lane), t = m16 tile, s = k16 step.
//   .x = (row=t*16+lane/4,   k=s*16+(lane%4)*2)  pair
//   .y = (row+8, k) ; .z = (row, k+8) ; .w = (row+8, k+8)
__global__ void k_convx(const float* __restrict__ x, int N, int T) {
    int i = blockIdx.x * blockDim.x + threadIdx.x;
    if (i >= T * 256) return;
    int t = i >> 8, s = (i >> 5) & 7, lane = i & 31;
    int rlo = t * 16 + (lane >> 2);
    int rhi = rlo + 8;
    int k0 = s * 16 + (lane & 3) * 2;
    float2 z = make_float2(0.f, 0.f);
    float2 v00 = (rlo < N) ? *(const float2*)(x + (size_t)rlo * DD + k0) : z;
    float2 v01 = (rlo < N) ? *(const float2*)(x + (size_t)rlo * DD + k0 + 8) : z;
    float2 v10 = (rhi < N) ? *(const float2*)(x + (size_t)rhi * DD + k0) : z;
    float2 v11 = (rhi < N) ? *(const float2*)(x + (size_t)rhi * DD + k0 + 8) : z;
    uint4 hi, lo;
    hi.x = pack_hi(v00.x, v00.y); lo.x = pack_lo(v00.x, v00.y);
    hi.y = pack_hi(v10.x, v10.y); lo.y = pack_lo(v10.x, v10.y);
    hi.z = pack_hi(v01.x, v01.y); lo.z = pack_lo(v01.x, v01.y);
    hi.w = pack_hi(v11.x, v11.y); lo.w = pack_lo(v11.x, v11.y);
    int idx = (t * 8 + s) * 32 + lane;
    ((uint4*)g_ahi)[idx] = hi;
    ((uint4*)g_alo)[idx] = lo;
}

// B fragment order: uint2 index ((s*16 + j)*32 + lane) per layer, j = n8 tile.
//   .x = (k=s*16+(lane%4)*2, n=j*8+lane/4) pair ; .y = (k+8, n) pair
__global__ void k_wprep(const float* __restrict__ lin_w) {
    int i = blockIdx.x * blockDim.x + threadIdx.x;
    if (i >= 3 * 8 * 16 * 32) return;
    int l = i >> 12;
    int s = (i >> 9) & 7;
    int j = (i >> 5) & 15;
    int lane = i & 31;
    int n = j * 8 + (lane >> 2);
    int k0 = s * 16 + (lane & 3) * 2;
    const float* W = lin_w + (size_t)l * DD * DD;
    float a0 = W[(size_t)k0 * DD + n],       a1 = W[(size_t)(k0 + 1) * DD + n];
    float b0 = W[(size_t)(k0 + 8) * DD + n], b1 = W[(size_t)(k0 + 9) * DD + n];
    uint2 hi, lo;
    hi.x = pack_hi(a0, a1); lo.x = pack_lo(a0, a1);
    hi.y = pack_hi(b0, b1); lo.y = pack_lo(b0, b1);
    int idx = (s * 16 + j) * 32 + lane;
    ((uint2*)g_bhi[l])[idx] = hi;
    ((uint2*)g_blo[l])[idx] = lo;
}

// ---------------- HMMA GEMM: ht = leaky_relu(A @ W + b), fused attention dots --
// CTA: 128 rows x 128 cols. 8 warps: warp_m = wid&3 (32-row strip), warp_n = wid>>2
// (64-col half). bf16x2 split: Ahi*Bhi + Ahi*Blo + Alo*Bhi.
__global__ __launch_bounds__(256, 1) void k_gemm_mma(
    const float* __restrict__ bias, const float* __restrict__ aw, int layer, int M)
{
    __shared__ float sdl[128], sdr[128];
    int tid = threadIdx.x, wid = tid >> 5, lane = tid & 31;
    int warp_m = wid & 3, warp_n = wid >> 2;
    int r0 = blockIdx.x * 128;
    int t0 = (r0 + warp_m * 32) >> 4;      // first m16 tile of this warp

    const uint4* Afh = (const uint4*)g_ahi;
    const uint4* Afl = (const uint4*)g_alo;
    const uint2* Bfh = (const uint2*)g_bhi[layer];
    const uint2* Bfl = (const uint2*)g_blo[layer];

    float acc[2][8][4];
#pragma unroll
    for (int t = 0; t < 2; t++)
#pragma unroll
        for (int j = 0; j < 8; j++)
#pragma unroll
            for (int r = 0; r < 4; r++) acc[t][j][r] = 0.f;

#pragma unroll
    for (int s = 0; s < 8; s++) {
        uint4 ah0 = Afh[(size_t)((t0 + 0) * 8 + s) * 32 + lane];
        uint4 ah1 = Afh[(size_t)((t0 + 1) * 8 + s) * 32 + lane];
        uint4 al0 = Afl[(size_t)((t0 + 0) * 8 + s) * 32 + lane];
        uint4 al1 = Afl[(size_t)((t0 + 1) * 8 + s) * 32 + lane];
        uint2 bh[8], bl[8];
#pragma unroll
        for (int j = 0; j < 8; j++) {
            int bidx = (s * 16 + warp_n * 8 + j) * 32 + lane;
            bh[j] = Bfh[bidx];
            bl[j] = Bfl[bidx];
        }
#pragma unroll
        for (int j = 0; j < 8; j++) {
            mma16816(acc[0][j], (const uint32_t*)&ah0, (const uint32_t*)&bh[j]);
            mma16816(acc[1][j], (const uint32_t*)&ah1, (const uint32_t*)&bh[j]);
            mma16816(acc[0][j], (const uint32_t*)&ah0, (const uint32_t*)&bl[j]);
            mma16816(acc[1][j], (const uint32_t*)&ah1, (const uint32_t*)&bl[j]);
            mma16816(acc[0][j], (const uint32_t*)&al0, (const uint32_t*)&bh[j]);
            mma16816(acc[1][j], (const uint32_t*)&al1, (const uint32_t*)&bh[j]);
        }
    }

    // epilogue: bias + leaky_relu + store ht + attention dots
    int l4 = lane >> 2, l2 = (lane & 3) * 2;
    float dls[2][2], drs[2][2];
#pragma unroll
    for (int t = 0; t < 2; t++) {
#pragma unroll
        for (int h = 0; h < 2; h++) {
            int rowl = warp_m * 32 + t * 16 + h * 8 + l4;
            int row = r0 + rowl;
            float dl = 0.f, dr = 0.f;
#pragma unroll
            for (int j = 0; j < 8; j++) {
                int c = warp_n * 64 + j * 8 + l2;
                float v0 = acc[t][j][h * 2 + 0] + bias[c];
                float v1 = acc[t][j][h * 2 + 1] + bias[c + 1];
                v0 = v0 > 0.f ? v0 : 0.2f * v0;
                v1 = v1 > 0.f ? v1 : 0.2f * v1;
                if (row < M) *(float2*)(g_ht + (size_t)row * DD + c) = make_float2(v0, v1);
                dl += v0 * aw[c] + v1 * aw[c + 1];
                dr += v0 * aw[DD + c] + v1 * aw[DD + c + 1];
            }
            dl += __shfl_xor_sync(0xffffffffu, dl, 1);
            dl += __shfl_xor_sync(0xffffffffu, dl, 2);
            dr += __shfl_xor_sync(0xffffffffu, dr, 1);
            dr += __shfl_xor_sync(0xffffffffu, dr, 2);
            dls[t][h] = dl; drs[t][h] = dr;
            if (warp_n == 0 && (lane & 3) == 0) { sdl[rowl] = dl; sdr[rowl] = dr; }
        }
    }
    __syncthreads();
    if (warp_n == 1 && (lane & 3) == 0) {
#pragma unroll
        for (int t = 0; t < 2; t++)
#pragma unroll
            for (int h = 0; h < 2; h++) {
                int rowl = warp_m * 32 + t * 16 + h * 8 + l4;
                int row = r0 + rowl;
                if (row < M) {
                    g_sl[row] = dls[t][h] + sdl[rowl];
                    g_sr[row] = drs[t][h] + sdr[rowl];
                }
            }
    }
}

// ---------------- per-node softmax + aggregation (warp per node) --------------
__global__ __launch_bounds__(256) void k_agg(
    float* __restrict__ extout, int last, const float* __restrict__ abp, int N)
{
    const float* ht = g_ht;
    int gw = (blockIdx.x * blockDim.x + threadIdx.x) >> 5;
    int lane = threadIdx.x & 31;
    if (gw >= N) return;

    int base = g_off[gw], end = g_off[gw + 1];
    int c4 = lane * 4;
    float4 acc = make_float4(0.f, 0.f, 0.f, 0.f);

    if (end > base) {
        float ab = *abp;
        float sli = g_sl[gw];
        float m = -1e30f, s = 0.f;
        for (int k = base + lane; k < end; k += 32) {
            int d = g_col[k];
            float e = sli + g_sr[d] + ab;
            if (e > m) { s = s * __expf(m - e) + 1.f; m = e; }
            else        { s += __expf(e - m); }
        }
#pragma unroll
        for (int o = 16; o; o >>= 1) {
            float mo = __shfl_xor_sync(0xffffffffu, m, o);
            float so = __shfl_xor_sync(0xffffffffu, s, o);
            float mn = fmaxf(m, mo);
            s = s * __expf(m - mn) + so * __expf(mo - mn);
            m = mn;
        }
        float inv = 1.f / s;
        float cshift = sli + ab - m;
        for (int k = base; k < end; k++) {
            int d = g_col[k];
            float w = __expf(cshift + g_sr[d]) * inv;
            float4 hv = *(const float4*)(ht + (size_t)d * DD + c4);
            acc.x += w * hv.x; acc.y += w * hv.y;
            acc.z += w * hv.z; acc.w += w * hv.w;
        }
    }
    acc.x = fmaxf(acc.x, 0.f);
    acc.y = fmaxf(acc.y, 0.f);
    acc.z = fmaxf(acc.z, 0.f);
    acc.w = fmaxf(acc.w, 0.f);

    if (last) {
        *(float4*)(extout + (size_t)gw * DD + c4) = acc;
    } else {
        // emit next-layer A fragments (hi/lo) for this row's 4 cols
        int t = gw >> 4, rr = gw & 15;
        int s = c4 >> 4;
        int ks0 = c4 & 15;
        int lanep = (rr & 7) * 4 + ((ks0 & 7) >> 1);
        int reg = ((rr >> 3) & 1) + ((ks0 >> 3) << 1);
        uint32_t* ah = (uint32_t*)g_ahi;
        uint32_t* al = (uint32_t*)g_alo;
        int b0 = (((t * 8 + s) * 32 + lanep) << 2) + reg;
        int b1 = (((t * 8 + s) * 32 + lanep + 1) << 2) + reg;
        ah[b0] = pack_hi(acc.x, acc.y); al[b0] = pack_lo(acc.x, acc.y);
        ah[b1] = pack_hi(acc.z, acc.w); al[b1] = pack_lo(acc.z, acc.w);
    }
}

// ---------------- launch ----------------
extern "C" void kernel_launch(void* const* d_in, const int* in_sizes, int n_in,
                              void* d_out, int out_size)
{
    const float* x      = (const float*)d_in[0];
    const int*   esrc   = (const int*)d_in[1];
    const int*   edst   = (const int*)d_in[2];
    const float* lin_w  = (const float*)d_in[3];
    const float* lin_b  = (const float*)d_in[4];
    const float* attn_w = (const float*)d_in[5];
    const float* attn_b = (const float*)d_in[6];

    int N = in_sizes[0] / DD;
    int E = in_sizes[1];
    int gB = (N + 127) / 128;          // GEMM CTAs
    int T = gB * 8;                    // m16 tiles incl. padding (covers gB*128 rows)

    // CSR build
    k_zero<<<(N + 255) / 256, 256>>>(N);
    k_count<<<(E + 255) / 256, 256>>>(esrc, E);
    k_scan<<<1, 1024>>>(N, E);
    k_scatter<<<(E + 255) / 256, 256>>>(esrc, edst, E);

    // fragment prep
    k_convx<<<T, 256>>>(x, N, T);
    k_wprep<<<(3 * 8 * 16 * 32 + 255) / 256, 256>>>(lin_w);

    int aB = (N + 7) / 8;
    for (int l = 0; l < 3; l++) {
        k_gemm_mma<<<gB, 256>>>(lin_b + (size_t)l * DD,
                                attn_w + (size_t)l * 2 * DD, l, N);
        k_agg<<<aB, 256>>>((float*)d_out, l == 2 ? 1 : 0, attn_b + l, N);
    }
}